// round 15
// baseline (speedup 1.0000x reference)
#include <cuda_runtime.h>
#include <math.h>
#include <stdint.h>

#define BATCH 4
#define IMG 224
#define NPIX (IMG*IMG)
#define N0 512
#define F0 4
#define N1 2048
#define F1 8
#define KPAD 576          // padded 3+512 -> 576 (Kc=144 at S=4, divisible by 16)
#define XLD 576
#define HLD 2048
#define DH 128

typedef unsigned long long ull;

// ------------------------- scratch -------------------------
__device__ float g_part[(size_t)4*4*1024*256];         // split-K partials / gemm1 raw out
__device__ float g_w1hi[1024*1152];
__device__ float g_w1mi[1024*1152];
__device__ float g_w1lo[1024*1152];
__device__ float g_tokThi[(size_t)BATCH*256*1152];     // [b][n][c], token0 dropped
__device__ float g_tokTmi[(size_t)BATCH*256*1152];
__device__ float g_tokTlo[(size_t)BATCH*256*1152];
__device__ float g_feat1T[(size_t)BATCH*256*1024];     // [b][n][m]
__device__ float g_lf[(size_t)BATCH*256*512];          // [b][cell][c]
__device__ float g_w2c[BATCH*12];
__device__ float g_w1p[2*DH*KPAD];                     // padded/reordered stage weights
__device__ int   g_pixb[BATCH*N1];
__device__ float g_pzb[BATCH*N1];
__device__ ull   g_zbuf[(size_t)2*BATCH*NPIX];         // double-buffered (stage0 / stage1)
__device__ float g_x[(size_t)BATCH*N1*XLD];            // [b][n][k]
__device__ float g_h[(size_t)BATCH*DH*HLD];

// ------------------------- helpers -------------------------
__device__ __forceinline__ void ffma2(ull &d, ull a, ull b){
    asm("fma.rn.f32x2 %0, %1, %2, %0;" : "+l"(d) : "l"(a), "l"(b));
}
__device__ __forceinline__ float2 unpack2(ull v){
    float2 r; asm("mov.b64 {%0,%1}, %2;" : "=f"(r.x), "=f"(r.y) : "l"(v)); return r;
}
__device__ __forceinline__ float tf32_rna(float a){
    uint32_t r; asm("cvt.rna.tf32.f32 %0, %1;" : "=r"(r) : "f"(a));
    return __uint_as_float(r);
}
__device__ __forceinline__ void split3(float a, float &h, float &m, float &l){
    h = tf32_rna(a);
    float r1 = a - h;
    m = tf32_rna(r1);
    l = tf32_rna(r1 - m);
}
__device__ __forceinline__ void mma_tf32(float* d, const float* a, const float* b){
    asm volatile(
        "mma.sync.aligned.m16n8k8.row.col.f32.tf32.tf32.f32 "
        "{%0,%1,%2,%3}, {%4,%5,%6,%7}, {%8,%9}, {%0,%1,%2,%3};"
        : "+f"(d[0]), "+f"(d[1]), "+f"(d[2]), "+f"(d[3])
        : "r"(__float_as_uint(a[0])), "r"(__float_as_uint(a[1])),
          "r"(__float_as_uint(a[2])), "r"(__float_as_uint(a[3])),
          "r"(__float_as_uint(b[0])), "r"(__float_as_uint(b[1])));
}

// ------------------------- 3-split TF32 mma.sync GEMM (exact to ~2^-33/product) -------------------------
// C[b](MxN) = A(MxK) @ (B[b](NxK))^T, 6 passes: hh + hm + mh + hl + lh + mm.
// Tile BM=64 x BN=32, 128 threads (4 warps 2m x 2n), warp tile 32x16. P=20 pitch (R9-verified layout).
__global__ __launch_bounds__(128) void gemm_mma3(
    const float* __restrict__ Ah, const float* __restrict__ Am, const float* __restrict__ Al,
    const float* __restrict__ Bh, const float* __restrict__ Bm, const float* __restrict__ Bl,
    float* __restrict__ C, int K, int ldc, size_t sB, size_t sC)
{
    constexpr int BN = 32, WN = 16, NF = 2, P = 20;
    __shared__ __align__(16) float SAH[2][64*P], SAM[2][64*P], SAL[2][64*P];
    __shared__ __align__(16) float SBH[2][BN*P], SBM[2][BN*P], SBL[2][BN*P];

    const int tid = threadIdx.x, lane = tid & 31, wid = tid >> 5;
    const int wm = wid & 1, wn = wid >> 1;
    const int m0 = blockIdx.y*64, n0 = blockIdx.x*BN, b = blockIdx.z;

    const float* pAh = Ah + (size_t)m0*K;
    const float* pAm = Am + (size_t)m0*K;
    const float* pAl = Al + (size_t)m0*K;
    const float* pBh = Bh + (size_t)b*sB + (size_t)n0*K;
    const float* pBm = Bm + (size_t)b*sB + (size_t)n0*K;
    const float* pBl = Bl + (size_t)b*sB + (size_t)n0*K;

    float acc[2][NF][4];
#pragma unroll
    for (int i = 0; i < 2; i++)
#pragma unroll
        for (int j = 0; j < NF; j++)
#pragma unroll
            for (int r = 0; r < 4; r++) acc[i][j][r] = 0.f;

    float4 rah[2], ram[2], ral[2], rbh, rbm, rbl;
    const int arow = tid >> 2, aq = tid & 3;

    auto ldChunk = [&](int t){
#pragma unroll
        for (int i = 0; i < 2; i++){
            size_t off = (size_t)(arow + i*32)*K + t*16 + aq*4;
            rah[i] = *(const float4*)(pAh + off);
            ram[i] = *(const float4*)(pAm + off);
            ral[i] = *(const float4*)(pAl + off);
        }
        {
            size_t off = (size_t)arow*K + t*16 + aq*4;   // arow 0..31 covers BN
            rbh = *(const float4*)(pBh + off);
            rbm = *(const float4*)(pBm + off);
            rbl = *(const float4*)(pBl + off);
        }
    };
    auto stChunk = [&](int buf){
#pragma unroll
        for (int i = 0; i < 2; i++){
            int r = arow + i*32;
            *(float4*)&SAH[buf][r*P + aq*4] = rah[i];
            *(float4*)&SAM[buf][r*P + aq*4] = ram[i];
            *(float4*)&SAL[buf][r*P + aq*4] = ral[i];
        }
        *(float4*)&SBH[buf][arow*P + aq*4] = rbh;
        *(float4*)&SBM[buf][arow*P + aq*4] = rbm;
        *(float4*)&SBL[buf][arow*P + aq*4] = rbl;
    };
    auto compute = [&](int buf){
#pragma unroll
        for (int ks = 0; ks < 2; ks++){
            const int kk = ks*8;
            float ah[2][4], am[2][4], al[2][4];
#pragma unroll
            for (int mf = 0; mf < 2; mf++){
                int r0 = (wm*32 + mf*16 + (lane>>2))*P + kk + (lane&3);
                ah[mf][0] = SAH[buf][r0];       ah[mf][1] = SAH[buf][r0 + 8*P];
                ah[mf][2] = SAH[buf][r0 + 4];   ah[mf][3] = SAH[buf][r0 + 8*P + 4];
                am[mf][0] = SAM[buf][r0];       am[mf][1] = SAM[buf][r0 + 8*P];
                am[mf][2] = SAM[buf][r0 + 4];   am[mf][3] = SAM[buf][r0 + 8*P + 4];
                al[mf][0] = SAL[buf][r0];       al[mf][1] = SAL[buf][r0 + 8*P];
                al[mf][2] = SAL[buf][r0 + 4];   al[mf][3] = SAL[buf][r0 + 8*P + 4];
            }
            float bh[NF][2], bm[NF][2], bl[NF][2];
#pragma unroll
            for (int nf = 0; nf < NF; nf++){
                int r0 = (wn*WN + nf*8 + (lane>>2))*P + kk + (lane&3);
                bh[nf][0] = SBH[buf][r0]; bh[nf][1] = SBH[buf][r0 + 4];
                bm[nf][0] = SBM[buf][r0]; bm[nf][1] = SBM[buf][r0 + 4];
                bl[nf][0] = SBL[buf][r0]; bl[nf][1] = SBL[buf][r0 + 4];
            }
#pragma unroll
            for (int mf = 0; mf < 2; mf++)
#pragma unroll
                for (int nf = 0; nf < NF; nf++){
                    mma_tf32(acc[mf][nf], ah[mf], bh[nf]);
                    mma_tf32(acc[mf][nf], ah[mf], bm[nf]);
                    mma_tf32(acc[mf][nf], am[mf], bh[nf]);
                    mma_tf32(acc[mf][nf], ah[mf], bl[nf]);
                    mma_tf32(acc[mf][nf], al[mf], bh[nf]);
                    mma_tf32(acc[mf][nf], am[mf], bm[nf]);
                }
        }
    };

    ldChunk(0); stChunk(0);
    __syncthreads();
    const int T = K / 16;
    for (int t = 0; t < T; ++t){
        const int buf = t & 1;
        if (t + 1 < T) ldChunk(t + 1);
        compute(buf);
        if (t + 1 < T) stChunk(buf ^ 1);
        __syncthreads();
    }

#pragma unroll
    for (int mf = 0; mf < 2; mf++)
#pragma unroll
        for (int nf = 0; nf < NF; nf++){
            int m = m0 + wm*32 + mf*16 + (lane>>2);
            int n = n0 + wn*WN + nf*8 + 2*(lane&3);
            *(float2*)&C[(size_t)b*sC + (size_t)m*ldc + n]     = make_float2(acc[mf][nf][0], acc[mf][nf][1]);
            *(float2*)&C[(size_t)b*sC + (size_t)(m+8)*ldc + n] = make_float2(acc[mf][nf][2], acc[mf][nf][3]);
        }
}

// ------------------------- k-pair packed-fp32 split-K GEMM (FFMA2, R7 core verbatim) -------------------------
template<int S>
__global__ __launch_bounds__(128, 4) void gemm_k(
    const float* __restrict__ A, const float* __restrict__ B,
    float* __restrict__ Cpart, int Kc, int lda, int ldb, int N, size_t sB)
{
    __shared__ __align__(16) float As[2][8][128];
    __shared__ __align__(16) float Bs[2][8][256];
    const int tid = threadIdx.x;
    const int m0 = blockIdx.y * 64;
    const int n0 = blockIdx.x * 64;
    const int M  = gridDim.y * 64;
    const int bz = blockIdx.z;
    const int b  = bz / S, s = bz % S;
    float* Cp = Cpart + (size_t)bz * ((size_t)M * N);
    const int tm = tid >> 4, tn = tid & 15;
    const int lm = tid & 63, lh = tid >> 6;

    const float* Ap = A + (size_t)(m0 + lm) * lda + (size_t)s * Kc + lh*8;
    const float* Bp = B + (size_t)b * sB + (size_t)(n0 + lm) * ldb + (size_t)s * Kc + lh*8;

    ull acc[8][4];
#pragma unroll
    for (int i = 0; i < 8; i++)
#pragma unroll
        for (int j = 0; j < 4; j++) acc[i][j] = 0ULL;

    float4 pa, pb;
    auto ldSet = [&](int tI, int set){
        pa = *(const float4*)(Ap + tI*16 + set*4);
        pb = *(const float4*)(Bp + tI*16 + set*4);
    };
    auto stSet = [&](int buf, int set){
        int kp = lh*4 + set*2;
        *(float2*)&As[buf][kp  ][2*lm] = make_float2(pa.x, pa.y);
        *(float2*)&As[buf][kp+1][2*lm] = make_float2(pa.z, pa.w);
        *(float2*)&Bs[buf][kp  ][2*lm] = make_float2(pb.x, pb.y);
        *(float2*)&Bs[buf][kp+1][2*lm] = make_float2(pb.z, pb.w);
    };
    auto compute = [&](int cur, int h){
        const float* asP = &As[cur][0][16*tm];
        const float* bsP = &Bs[cur][0][4*tn];
#pragma unroll
        for (int kp = 4*h; kp < 4*h + 4; ++kp){
            ull av[8];
#pragma unroll
            for (int i = 0; i < 4; i++){
                longlong2 aa = *(const longlong2*)(asP + kp*128 + 4*i);
                av[2*i] = (ull)aa.x; av[2*i+1] = (ull)aa.y;
            }
            ull bv[4];
#pragma unroll
            for (int q = 0; q < 2; q++){
                longlong2 bb = *(const longlong2*)(bsP + kp*256 + 64*q);
                bv[2*q] = (ull)bb.x; bv[2*q+1] = (ull)bb.y;
            }
#pragma unroll
            for (int i = 0; i < 8; i++)
#pragma unroll
                for (int j = 0; j < 4; j++) ffma2(acc[i][j], av[i], bv[j]);
        }
    };

    ldSet(0, 0); stSet(0, 0);
    ldSet(0, 1); stSet(0, 1);
    __syncthreads();

    const int T = Kc / 16;
    for (int t = 0; t < T; ++t){
        const int cur = t & 1, nxt = cur ^ 1;
        const int tN = (t + 1 < T) ? (t + 1) : t;
        ldSet(tN, 0);
        compute(cur, 0);
        stSet(nxt, 0);
        ldSet(tN, 1);
        compute(cur, 1);
        stSet(nxt, 1);
        __syncthreads();
    }

#pragma unroll
    for (int i = 0; i < 8; i++){
        int m = m0 + tm*8 + i;
#pragma unroll
        for (int q = 0; q < 2; q++){
            float2 v0 = unpack2(acc[i][2*q]);
            float2 v1 = unpack2(acc[i][2*q+1]);
            int n = n0 + 2*tn + 32*q;
            *(float2*)&Cp[(size_t)m*N + n] = make_float2(v0.x + v0.y, v1.x + v1.y);
        }
    }
}

// ------------------------- split-K reduce + bias + activation -------------------------
template<int S>
__global__ __launch_bounds__(256) void reduce_act(
    const float* __restrict__ part, const float* __restrict__ bias,
    float* __restrict__ C, int M, int N, int ldc, size_t sC, int relu)
{
    const int b = blockIdx.y;
    const int idx = blockIdx.x*256 + threadIdx.x;
    const int total = M*N/4;
    if (idx >= total) return;
    const int m = (idx*4) / N, n = (idx*4) % N;
    const float4* p = (const float4*)(part + (size_t)b*S*M*N);
    float4 a = p[idx];
#pragma unroll
    for (int s = 1; s < S; s++){
        float4 v = p[idx + (size_t)s*total];
        a.x += v.x; a.y += v.y; a.z += v.z; a.w += v.w;
    }
    float bv = bias[m];
    a.x += bv; a.y += bv; a.z += bv; a.w += bv;
    if (relu){
        a.x = fmaxf(a.x, 0.f); a.y = fmaxf(a.y, 0.f);
        a.z = fmaxf(a.z, 0.f); a.w = fmaxf(a.w, 0.f);
    }
    *(float4*)&C[(size_t)b*sC + (size_t)m*ldc + n] = a;
}

// ------------------------- split-K reduce + bias + act + TRANSPOSE -------------------------
template<int S>
__global__ void reduce_act_T(
    const float* __restrict__ part, const float* __restrict__ bias,
    float* __restrict__ outT, int M, int N, int ldo, size_t sO, int relu)
{
    __shared__ float sm[32][33];
    const int b = blockIdx.z;
    const int m0 = blockIdx.x*32, n0 = blockIdx.y*32;
    const int x = threadIdx.x, y = threadIdx.y;
    const float* p = part + (size_t)b*S*M*N;
#pragma unroll
    for (int r = 0; r < 32; r += 8){
        int m = m0 + y + r;
        float a = 0.f;
        for (int s = 0; s < S; s++) a += p[(size_t)s*M*N + (size_t)m*N + n0 + x];
        a += bias[m];
        if (relu) a = fmaxf(a, 0.f);
        sm[y+r][x] = a;
    }
    __syncthreads();
#pragma unroll
    for (int r = 0; r < 32; r += 8)
        outT[(size_t)b*sO + (size_t)(n0 + y + r)*ldo + m0 + x] = sm[x][y+r];
}

// ------------------------- fused prep -------------------------
#define ZBLKS  (2*BATCH*NPIX/256)        // 1568
#define PWBLKS (2*DH*KPAD/256)           // 576
#define TTBLKS (8*36*BATCH)              // 1152
#define W1BLKS (1024*1152/256)           // 4608
#define PREP_BLOCKS (ZBLKS + PWBLKS + 1 + TTBLKS + W1BLKS)

__global__ void prep(const float* __restrict__ c2w,
                     const float* __restrict__ w0, const float* __restrict__ w1s,
                     const float* __restrict__ tokens, const float* __restrict__ w1)
{
    __shared__ float sm[32][33];
    int blk = blockIdx.x;
    const int tid = threadIdx.x;

    if (blk < ZBLKS){                      // zero both z-buffers
        g_zbuf[(size_t)blk*256 + tid] = ~0ULL;
        return;
    }
    blk -= ZBLKS;
    if (blk < PWBLKS){                     // pad/reorder stage weights
        int i = blk*256 + tid;
        int s = i / (DH*KPAD);
        int r = i - s*(DH*KPAD);
        int m = r / KPAD, k = r - m*KPAD;
        const float* w = s ? w1s : w0;
        float v = 0.f;
        if (k < 512) v = w[m*515 + 3 + k];
        else if (k < 515) v = w[m*515 + (k - 512)];
        g_w1p[i] = v;
        return;
    }
    blk -= PWBLKS;
    if (blk == 0){                         // camera inverse
        int b = tid;
        if (b >= BATCH) return;
        float m[4][4], inv[4][4];
        for (int r = 0; r < 4; r++)
            for (int c = 0; c < 4; c++){
                float v = c2w[b*16 + r*4 + c];
                if (r < 3 && (c == 1 || c == 2)) v = -v;
                m[r][c] = v;
                inv[r][c] = (r == c) ? 1.f : 0.f;
            }
        for (int col = 0; col < 4; col++){
            int piv = col; float best = fabsf(m[col][col]);
            for (int r = col+1; r < 4; r++){ float a = fabsf(m[r][col]); if (a > best){ best = a; piv = r; } }
            if (piv != col)
                for (int c = 0; c < 4; c++){
                    float t = m[col][c]; m[col][c] = m[piv][c]; m[piv][c] = t;
                    t = inv[col][c]; inv[col][c] = inv[piv][c]; inv[piv][c] = t;
                }
            float d = 1.f / m[col][col];
            for (int c = 0; c < 4; c++){ m[col][c] *= d; inv[col][c] *= d; }
            for (int r = 0; r < 4; r++)
                if (r != col){
                    float f = m[r][col];
                    for (int c = 0; c < 4; c++){ m[r][c] -= f*m[col][c]; inv[r][c] -= f*inv[col][c]; }
                }
        }
        for (int i = 0; i < 12; i++) g_w2c[b*12 + i] = inv[i/4][i%4];
        return;
    }
    blk -= 1;
    if (blk < TTBLKS){                     // transpose tokens (token0 dropped) -> 3-split tf32
        int n0 = (blk & 7)*32;
        int c0 = ((blk >> 3) % 36)*32;
        int b  = blk / 288;
        int x = tid & 31, y = tid >> 5;
#pragma unroll
        for (int r = 0; r < 32; r += 8)
            sm[y+r][x] = tokens[((size_t)b*1152 + c0 + y + r)*257 + n0 + x + 1];
        __syncthreads();
#pragma unroll
        for (int r = 0; r < 32; r += 8){
            float v = sm[x][y+r];
            float h, m_, l;
            split3(v, h, m_, l);
            size_t o = ((size_t)b*256 + n0 + y + r)*1152 + c0 + x;
            g_tokThi[o] = h; g_tokTmi[o] = m_; g_tokTlo[o] = l;
        }
        return;
    }
    blk -= TTBLKS;
    {                                      // w1 3-split
        int i = blk*256 + tid;
        float v = w1[i];
        float h, m_, l;
        split3(v, h, m_, l);
        g_w1hi[i] = h; g_w1mi[i] = m_; g_w1lo[i] = l;
    }
}

// ------------------------- z-buffer projection -------------------------
__global__ void project(const float* __restrict__ pts, const float* __restrict__ Kin,
                        int Npts, int zhalf){
    int i = blockIdx.x*256 + threadIdx.x;
    if (i >= BATCH*Npts) return;
    int b = i / Npts, n = i - b*Npts;
    const float* w = g_w2c + b*12;
    float x = pts[(size_t)i*3], y = pts[(size_t)i*3+1], z = pts[(size_t)i*3+2];
    float camx = w[0]*x + w[1]*y + w[2]*z + w[3];
    float camy = w[4]*x + w[5]*y + w[6]*z + w[7];
    float camz = w[8]*x + w[9]*y + w[10]*z + w[11];
    float zs = (fabsf(camz) > 1e-8f) ? camz : 1e-8f;
    float fx = Kin[b*9+0], cxk = Kin[b*9+2], fy = Kin[b*9+4], cyk = Kin[b*9+5];
    float px = fx*camx/zs + cxk;
    float py = fy*camy/zs + cyk;
    int ix = (int)floorf(px), iy = (int)floorf(py);
    bool valid = (camz > 1e-6f) && ix >= 0 && ix < IMG && iy >= 0 && iy < IMG;
    int pix = valid ? iy*IMG + ix : -1;
    g_pixb[b*N1 + n] = pix;
    g_pzb[b*N1 + n] = camz;
    if (valid)
        atomicMin(&g_zbuf[((size_t)zhalf*BATCH + b)*NPIX + pix],
                  ((ull)__float_as_uint(camz) << 32) | (unsigned)n);
}

// ------------------------- gather cond + visibility check -------------------------
__global__ __launch_bounds__(128) void gather_cond(const float* __restrict__ pts,
                                                   int Npts, int zhalf){
    int blk = blockIdx.x;
    int b = blk / Npts, n = blk - b*Npts;
    int tid = threadIdx.x;
    float* xo = g_x + ((size_t)b*N1 + n)*XLD;
    if (tid < 3) xo[512 + tid] = pts[(size_t)blk*3 + tid];
    int pix = g_pixb[b*N1 + n];
    bool vis = false;
    if (pix >= 0){
        ull key = ((ull)__float_as_uint(g_pzb[b*N1 + n]) << 32) | (unsigned)n;
        vis = (g_zbuf[((size_t)zhalf*BATCH + b)*NPIX + pix] == key);
    }
    if (!vis){
        *(float4*)&xo[tid*4] = make_float4(0.f, 0.f, 0.f, 0.f);
        return;
    }
    int iy = pix / IMG, ix = pix - iy*IMG;
    float sfx = (ix + 0.5f)*(16.f/224.f) - 0.5f;
    float sfy = (iy + 0.5f)*(16.f/224.f) - 0.5f;
    int jx0 = (int)floorf(sfx); float fxw = sfx - (float)jx0;
    int jy0 = (int)floorf(sfy); float fyw = sfy - (float)jy0;
    int x0 = min(max(jx0, 0), 15), x1 = min(max(jx0+1, 0), 15);
    int y0 = min(max(jy0, 0), 15), y1 = min(max(jy0+1, 0), 15);
    float w00 = (1.f-fyw)*(1.f-fxw), w01 = (1.f-fyw)*fxw;
    float w10 = fyw*(1.f-fxw),       w11 = fyw*fxw;
    const float4* l00 = (const float4*)(g_lf + ((size_t)b*256 + y0*16 + x0)*512);
    const float4* l01 = (const float4*)(g_lf + ((size_t)b*256 + y0*16 + x1)*512);
    const float4* l10 = (const float4*)(g_lf + ((size_t)b*256 + y1*16 + x0)*512);
    const float4* l11 = (const float4*)(g_lf + ((size_t)b*256 + y1*16 + x1)*512);
    float4 v00 = l00[tid], v01 = l01[tid], v10 = l10[tid], v11 = l11[tid];
    float4 o;
    o.x = w00*v00.x + w01*v01.x + w10*v10.x + w11*v11.x;
    o.y = w00*v00.y + w01*v01.y + w10*v10.y + w11*v11.y;
    o.z = w00*v00.z + w01*v01.z + w10*v10.z + w11*v11.z;
    o.w = w00*v00.w + w01*v01.w + w10*v10.w + w11*v11.w;
    *(float4*)&xo[tid*4] = o;
}

// ------------------------- stage-0 output head + FUSED stage-1 projection -------------------------
__global__ __launch_bounds__(128) void stage_out0_proj(
    const float* __restrict__ ow, const float* __restrict__ ob,
    const float* __restrict__ pts_in, float* __restrict__ pts_out,
    const float* __restrict__ Kin)
{
    __shared__ float s_ow[F0*3][DH];
    __shared__ float s_ob[F0*3];
    const int b = blockIdx.y;
    const int tid = threadIdx.x;
    for (int i = tid; i < F0*3*DH; i += 128) s_ow[i / DH][i % DH] = ow[i];
    if (tid < F0*3) s_ob[tid] = ob[tid];
    __syncthreads();
    const int n = blockIdx.x*128 + tid;
    const float* hp = g_h + (size_t)b*DH*HLD;
    float acc[F0*3];
#pragma unroll
    for (int r = 0; r < F0*3; r++) acc[r] = s_ob[r];
    for (int o = 0; o < DH; o++){
        float hv = hp[(size_t)o*HLD + n];
#pragma unroll
        for (int r = 0; r < F0*3; r++) acc[r] += s_ow[r][o] * hv;
    }
    float p[3];
    p[0] = pts_in[(size_t)(b*N0 + n)*3 + 0];
    p[1] = pts_in[(size_t)(b*N0 + n)*3 + 1];
    p[2] = pts_in[(size_t)(b*N0 + n)*3 + 2];

    const float* w = g_w2c + b*12;
    const float fx = Kin[b*9+0], cxk = Kin[b*9+2];
    const float fy = Kin[b*9+4], cyk = Kin[b*9+5];

#pragma unroll
    for (int k = 0; k < F0; k++){
        float o3[3];
#pragma unroll
        for (int c = 0; c < 3; c++){
            o3[c] = p[c] + tanhf(acc[k*3 + c]);
            pts_out[((size_t)b*N0*F0 + (size_t)n*F0 + k)*3 + c] = o3[c];
        }
        float camx = w[0]*o3[0] + w[1]*o3[1] + w[2]*o3[2] + w[3];
        float camy = w[4]*o3[0] + w[5]*o3[1] + w[6]*o3[2] + w[7];
        float camz = w[8]*o3[0] + w[9]*o3[1] + w[10]*o3[2] + w[11];
        float zs = (fabsf(camz) > 1e-8f) ? camz : 1e-8f;
        float px = fx*camx/zs + cxk;
        float py = fy*camy/zs + cyk;
        int ix = (int)floorf(px), iy = (int)floorf(py);
        bool valid = (camz > 1e-6f) && ix >= 0 && ix < IMG && iy >= 0 && iy < IMG;
        int pix = valid ? iy*IMG + ix : -1;
        int idx = n*F0 + k;
        g_pixb[b*N1 + idx] = pix;
        g_pzb[b*N1 + idx] = camz;
        if (valid)
            atomicMin(&g_zbuf[((size_t)1*BATCH + b)*NPIX + pix],
                      ((ull)__float_as_uint(camz) << 32) | (unsigned)idx);
    }
}

// ------------------------- stage-1 output head -------------------------
template <int F>
__global__ __launch_bounds__(128) void stage_out(
    const float* __restrict__ ow, const float* __restrict__ ob,
    const float* __restrict__ pts_in, float* __restrict__ pts_out, int Npts)
{
    __shared__ float s_ow[F*3][DH];
    __shared__ float s_ob[F*3];
    const int b = blockIdx.y;
    const int tid = threadIdx.x;
    for (int i = tid; i < F*3*DH; i += 128) s_ow[i / DH][i % DH] = ow[i];
    if (tid < F*3) s_ob[tid] = ob[tid];
    __syncthreads();
    const int n = blockIdx.x*128 + tid;
    if (n >= Npts) return;
    const float* hp = g_h + (size_t)b*DH*HLD;
    float acc[F*3];
#pragma unroll
    for (int r = 0; r < F*3; r++) acc[r] = s_ob[r];
    for (int o = 0; o < DH; o++){
        float hv = hp[(size_t)o*HLD + n];
#pragma unroll
        for (int r = 0; r < F*3; r++) acc[r] += s_ow[r][o] * hv;
    }
    float p[3];
    p[0] = pts_in[(size_t)(b*Npts + n)*3 + 0];
    p[1] = pts_in[(size_t)(b*Npts + n)*3 + 1];
    p[2] = pts_in[(size_t)(b*Npts + n)*3 + 2];
#pragma unroll
    for (int k = 0; k < F; k++)
#pragma unroll
        for (int c = 0; c < 3; c++){
            size_t oidx = ((size_t)b*Npts*F + (size_t)n*F + k)*3 + c;
            pts_out[oidx] = p[c] + tanhf(acc[k*3 + c]);
        }
}

// ------------------------- launch -------------------------
extern "C" void kernel_launch(void* const* d_in, const int* in_sizes, int n_in,
                              void* d_out, int out_size)
{
    const float* points = (const float*)d_in[0];
    const float* tokens = (const float*)d_in[1];
    const float* c2w    = (const float*)d_in[2];
    const float* Kin    = (const float*)d_in[3];
    const float* w1     = (const float*)d_in[4];
    const float* b1     = (const float*)d_in[5];
    const float* w2     = (const float*)d_in[6];
    const float* b2     = (const float*)d_in[7];
    const float* s0w1   = (const float*)d_in[8];
    const float* s0b1   = (const float*)d_in[9];
    const float* s0ow   = (const float*)d_in[10];
    const float* s0ob   = (const float*)d_in[11];
    const float* s1w1   = (const float*)d_in[12];
    const float* s1b1   = (const float*)d_in[13];
    const float* s1ow   = (const float*)d_in[14];
    const float* s1ob   = (const float*)d_in[15];

    float* out0 = (float*)d_out;
    float* out1 = out0 + (size_t)BATCH*N0*F0*3;

    float *part, *feat1T, *lfbuf, *w1p, *xbuf, *hbuf;
    float *w1hi, *w1mi, *w1lo, *tkh, *tkm, *tkl;
    cudaGetSymbolAddress((void**)&part,   g_part);
    cudaGetSymbolAddress((void**)&feat1T, g_feat1T);
    cudaGetSymbolAddress((void**)&lfbuf,  g_lf);
    cudaGetSymbolAddress((void**)&w1p,    g_w1p);
    cudaGetSymbolAddress((void**)&xbuf,   g_x);
    cudaGetSymbolAddress((void**)&hbuf,   g_h);
    cudaGetSymbolAddress((void**)&w1hi,   g_w1hi);
    cudaGetSymbolAddress((void**)&w1mi,   g_w1mi);
    cudaGetSymbolAddress((void**)&w1lo,   g_w1lo);
    cudaGetSymbolAddress((void**)&tkh,    g_tokThi);
    cudaGetSymbolAddress((void**)&tkm,    g_tokTmi);
    cudaGetSymbolAddress((void**)&tkl,    g_tokTlo);

    // 1 — all preparation (zbuf x2, weight pad, camera, token transpose+3split, w1 3split)
    prep<<<PREP_BLOCKS, 256>>>(c2w, s0w1, s1w1, tokens, w1);

    // gemm1 on mma.sync 3-split TF32 (exact to ~2^-33/product), no split-K
    gemm_mma3<<<dim3(8, 16, BATCH), 128>>>(w1hi, w1mi, w1lo, tkh, tkm, tkl,
        part, 1152, 256, (size_t)256*1152, (size_t)1024*256);
    reduce_act_T<1><<<dim3(1024/32, 256/32, BATCH), dim3(32, 8)>>>(part, b1, feat1T,
        1024, 256, 1024, (size_t)256*1024, 1);
    // gemm2 stays FFMA2
    gemm_k<8><<<dim3(4, 8, BATCH*8), 128>>>(w2, feat1T, part,
        1024/8, 1024, 1024, 256, (size_t)256*1024);
    reduce_act_T<8><<<dim3(512/32, 256/32, BATCH), dim3(32, 8)>>>(part, b2, lfbuf,
        512, 256, 512, (size_t)256*512, 0);

    // stage 0 (zbuf half 0)
    project<<<(BATCH*N0 + 255)/256, 256>>>(points, Kin, N0, 0);
    gather_cond<<<BATCH*N0, 128>>>(points, N0, 0);
    gemm_k<4><<<dim3(8, 2, BATCH*4), 128>>>(w1p, xbuf, part,
        KPAD/4, KPAD, XLD, 512, (size_t)N1*XLD);
    reduce_act<4><<<dim3(128*512/4/256, BATCH), 256>>>(part, s0b1, hbuf,
        128, 512, HLD, (size_t)DH*HLD, 1);
    stage_out0_proj<<<dim3(N0/128, BATCH), 128>>>(s0ow, s0ob, points, out0, Kin);

    // stage 1 (projection fused into stage_out0_proj)
    gather_cond<<<BATCH*N1, 128>>>(out0, N1, 1);
    gemm_k<4><<<dim3(32, 2, BATCH*4), 128>>>(w1p + DH*KPAD, xbuf, part,
        KPAD/4, KPAD, XLD, 2048, (size_t)N1*XLD);
    reduce_act<4><<<dim3(128*2048/4/256, BATCH), 256>>>(part, s1b1, hbuf,
        128, 2048, HLD, (size_t)DH*HLD, 1);
    stage_out<F1><<<dim3(N1/128, BATCH), 128>>>(s1ow, s1ob, out0, out1, N1);
}

// round 16
// speedup vs baseline: 1.4021x; 1.4021x over previous
#include <cuda_runtime.h>
#include <math.h>
#include <stdint.h>

#define BATCH 4
#define IMG 224
#define NPIX (IMG*IMG)
#define N0 512
#define F0 4
#define N1 2048
#define F1 8
#define KPAD 576          // padded 3+512 -> 576 (Kc=144 at S=4, divisible by 16)
#define XLD 576
#define HLD 2048
#define DH 128

typedef unsigned long long ull;

// ------------------------- scratch -------------------------
__device__ float g_part[(size_t)4*4*1024*256];         // split-K partials
__device__ float g_tokT[(size_t)BATCH*256*1152];       // [b][n][c] transposed tokens (token0 dropped)
__device__ float g_feat1T[(size_t)BATCH*256*1024];     // [b][n][m]
__device__ float g_lf[(size_t)BATCH*256*512];          // [b][cell][c]
__device__ float g_w2c[BATCH*12];
__device__ float g_w1p[2*DH*KPAD];                     // padded/reordered stage weights
__device__ int   g_pixb[BATCH*N1];
__device__ float g_pzb[BATCH*N1];
__device__ ull   g_zbuf[(size_t)2*BATCH*NPIX];         // double-buffered (stage0 / stage1)
__device__ float g_x[(size_t)BATCH*N1*XLD];            // [b][n][k]
__device__ float g_h[(size_t)BATCH*DH*HLD];

// ------------------------- helpers -------------------------
__device__ __forceinline__ void ffma2(ull &d, ull a, ull b){
    asm("fma.rn.f32x2 %0, %1, %2, %0;" : "+l"(d) : "l"(a), "l"(b));
}
__device__ __forceinline__ float2 unpack2(ull v){
    float2 r; asm("mov.b64 {%0,%1}, %2;" : "=f"(r.x), "=f"(r.y) : "l"(v)); return r;
}

// ------------------------- k-pair packed-fp32 split-K GEMM, 64x64 tile, KTILE=16 -------------------------
// (R7 core verbatim — known-good at 4 blocks/SM, regs 128, no spills.)
template<int S>
__global__ __launch_bounds__(128, 4) void gemm_k(
    const float* __restrict__ A, const float* __restrict__ B,
    float* __restrict__ Cpart, int Kc, int lda, int ldb, int N, size_t sB)
{
    __shared__ __align__(16) float As[2][8][128];
    __shared__ __align__(16) float Bs[2][8][256];
    const int tid = threadIdx.x;
    const int m0 = blockIdx.y * 64;
    const int n0 = blockIdx.x * 64;
    const int M  = gridDim.y * 64;
    const int bz = blockIdx.z;
    const int b  = bz / S, s = bz % S;
    float* Cp = Cpart + (size_t)bz * ((size_t)M * N);
    const int tm = tid >> 4, tn = tid & 15;
    const int lm = tid & 63, lh = tid >> 6;

    const float* Ap = A + (size_t)(m0 + lm) * lda + (size_t)s * Kc + lh*8;
    const float* Bp = B + (size_t)b * sB + (size_t)(n0 + lm) * ldb + (size_t)s * Kc + lh*8;

    ull acc[8][4];
#pragma unroll
    for (int i = 0; i < 8; i++)
#pragma unroll
        for (int j = 0; j < 4; j++) acc[i][j] = 0ULL;

    float4 pa, pb;
    auto ldSet = [&](int tI, int set){
        pa = *(const float4*)(Ap + tI*16 + set*4);
        pb = *(const float4*)(Bp + tI*16 + set*4);
    };
    auto stSet = [&](int buf, int set){
        int kp = lh*4 + set*2;
        *(float2*)&As[buf][kp  ][2*lm] = make_float2(pa.x, pa.y);
        *(float2*)&As[buf][kp+1][2*lm] = make_float2(pa.z, pa.w);
        *(float2*)&Bs[buf][kp  ][2*lm] = make_float2(pb.x, pb.y);
        *(float2*)&Bs[buf][kp+1][2*lm] = make_float2(pb.z, pb.w);
    };
    auto compute = [&](int cur, int h){
        const float* asP = &As[cur][0][16*tm];
        const float* bsP = &Bs[cur][0][4*tn];
#pragma unroll
        for (int kp = 4*h; kp < 4*h + 4; ++kp){
            ull av[8];
#pragma unroll
            for (int i = 0; i < 4; i++){
                longlong2 aa = *(const longlong2*)(asP + kp*128 + 4*i);
                av[2*i] = (ull)aa.x; av[2*i+1] = (ull)aa.y;
            }
            ull bv[4];
#pragma unroll
            for (int q = 0; q < 2; q++){
                longlong2 bb = *(const longlong2*)(bsP + kp*256 + 64*q);
                bv[2*q] = (ull)bb.x; bv[2*q+1] = (ull)bb.y;
            }
#pragma unroll
            for (int i = 0; i < 8; i++)
#pragma unroll
                for (int j = 0; j < 4; j++) ffma2(acc[i][j], av[i], bv[j]);
        }
    };

    ldSet(0, 0); stSet(0, 0);
    ldSet(0, 1); stSet(0, 1);
    __syncthreads();

    const int T = Kc / 16;
    for (int t = 0; t < T; ++t){
        const int cur = t & 1, nxt = cur ^ 1;
        const int tN = (t + 1 < T) ? (t + 1) : t;
        ldSet(tN, 0);
        compute(cur, 0);
        stSet(nxt, 0);
        ldSet(tN, 1);
        compute(cur, 1);
        stSet(nxt, 1);
        __syncthreads();
    }

#pragma unroll
    for (int i = 0; i < 8; i++){
        int m = m0 + tm*8 + i;
#pragma unroll
        for (int q = 0; q < 2; q++){
            float2 v0 = unpack2(acc[i][2*q]);
            float2 v1 = unpack2(acc[i][2*q+1]);
            int n = n0 + 2*tn + 32*q;
            *(float2*)&Cp[(size_t)m*N + n] = make_float2(v0.x + v0.y, v1.x + v1.y);
        }
    }
}

// ------------------------- split-K reduce + bias + activation (row-major out) -------------------------
template<int S>
__global__ __launch_bounds__(256) void reduce_act(
    const float* __restrict__ part, const float* __restrict__ bias,
    float* __restrict__ C, int M, int N, int ldc, size_t sC, int relu)
{
    const int b = blockIdx.y;
    const int idx = blockIdx.x*256 + threadIdx.x;
    const int total = M*N/4;
    if (idx >= total) return;
    const int m = (idx*4) / N, n = (idx*4) % N;
    const float4* p = (const float4*)(part + (size_t)b*S*M*N);
    float4 a = p[idx];
#pragma unroll
    for (int s = 1; s < S; s++){
        float4 v = p[idx + (size_t)s*total];
        a.x += v.x; a.y += v.y; a.z += v.z; a.w += v.w;
    }
    float bv = bias[m];
    a.x += bv; a.y += bv; a.z += bv; a.w += bv;
    if (relu){
        a.x = fmaxf(a.x, 0.f); a.y = fmaxf(a.y, 0.f);
        a.z = fmaxf(a.z, 0.f); a.w = fmaxf(a.w, 0.f);
    }
    *(float4*)&C[(size_t)b*sC + (size_t)m*ldc + n] = a;
}

// ------------------------- split-K reduce + bias + act + TRANSPOSE (out[n][m]) -------------------------
template<int S>
__global__ void reduce_act_T(
    const float* __restrict__ part, const float* __restrict__ bias,
    float* __restrict__ outT, int M, int N, int ldo, size_t sO, int relu)
{
    __shared__ float sm[32][33];
    const int b = blockIdx.z;
    const int m0 = blockIdx.x*32, n0 = blockIdx.y*32;
    const int x = threadIdx.x, y = threadIdx.y;
    const float* p = part + (size_t)b*S*M*N;
#pragma unroll
    for (int r = 0; r < 32; r += 8){
        int m = m0 + y + r;
        float a = 0.f;
        for (int s = 0; s < S; s++) a += p[(size_t)s*M*N + (size_t)m*N + n0 + x];
        a += bias[m];
        if (relu) a = fmaxf(a, 0.f);
        sm[y+r][x] = a;
    }
    __syncthreads();
#pragma unroll
    for (int r = 0; r < 32; r += 8)
        outT[(size_t)b*sO + (size_t)(n0 + y + r)*ldo + m0 + x] = sm[x][y+r];
}

// ------------------------- fused prep: zbuf resets + pad_w + setup_w2c + transpose_tok -------------------------
#define ZBLKS  (2*BATCH*NPIX/256)        // 1568 (exact)
#define PWBLKS (2*DH*KPAD/256)           // 576 (exact)
#define TTBLKS (8*36*BATCH)              // 1152
#define PREP_BLOCKS (ZBLKS + PWBLKS + 1 + TTBLKS)

__global__ void prep(const float* __restrict__ c2w,
                     const float* __restrict__ w0, const float* __restrict__ w1s,
                     const float* __restrict__ tokens)
{
    __shared__ float sm[32][33];
    int blk = blockIdx.x;
    const int tid = threadIdx.x;

    if (blk < ZBLKS){                      // zero both z-buffers
        g_zbuf[(size_t)blk*256 + tid] = ~0ULL;
        return;
    }
    blk -= ZBLKS;
    if (blk < PWBLKS){                     // pad/reorder stage weights
        int i = blk*256 + tid;
        int s = i / (DH*KPAD);
        int r = i - s*(DH*KPAD);
        int m = r / KPAD, k = r - m*KPAD;
        const float* w = s ? w1s : w0;
        float v = 0.f;
        if (k < 512) v = w[m*515 + 3 + k];
        else if (k < 515) v = w[m*515 + (k - 512)];
        g_w1p[i] = v;
        return;
    }
    blk -= PWBLKS;
    if (blk == 0){                         // camera inverse
        int b = tid;
        if (b >= BATCH) return;
        float m[4][4], inv[4][4];
        for (int r = 0; r < 4; r++)
            for (int c = 0; c < 4; c++){
                float v = c2w[b*16 + r*4 + c];
                if (r < 3 && (c == 1 || c == 2)) v = -v;
                m[r][c] = v;
                inv[r][c] = (r == c) ? 1.f : 0.f;
            }
        for (int col = 0; col < 4; col++){
            int piv = col; float best = fabsf(m[col][col]);
            for (int r = col+1; r < 4; r++){ float a = fabsf(m[r][col]); if (a > best){ best = a; piv = r; } }
            if (piv != col)
                for (int c = 0; c < 4; c++){
                    float t = m[col][c]; m[col][c] = m[piv][c]; m[piv][c] = t;
                    t = inv[col][c]; inv[col][c] = inv[piv][c]; inv[piv][c] = t;
                }
            float d = 1.f / m[col][col];
            for (int c = 0; c < 4; c++){ m[col][c] *= d; inv[col][c] *= d; }
            for (int r = 0; r < 4; r++)
                if (r != col){
                    float f = m[r][col];
                    for (int c = 0; c < 4; c++){ m[r][c] -= f*m[col][c]; inv[r][c] -= f*inv[col][c]; }
                }
        }
        for (int i = 0; i < 12; i++) g_w2c[b*12 + i] = inv[i/4][i%4];
        return;
    }
    blk -= 1;
    {                                      // transpose tokens (token0 dropped)
        int n0 = (blk & 7)*32;
        int c0 = ((blk >> 3) % 36)*32;
        int b  = blk / 288;
        int x = tid & 31, y = tid >> 5;
#pragma unroll
        for (int r = 0; r < 32; r += 8)
            sm[y+r][x] = tokens[((size_t)b*1152 + c0 + y + r)*257 + n0 + x + 1];
        __syncthreads();
#pragma unroll
        for (int r = 0; r < 32; r += 8)
            g_tokT[((size_t)b*256 + n0 + y + r)*1152 + c0 + x] = sm[x][y+r];
    }
}

// ------------------------- z-buffer projection -------------------------
__global__ void project(const float* __restrict__ pts, const float* __restrict__ Kin,
                        int Npts, int zhalf){
    int i = blockIdx.x*256 + threadIdx.x;
    if (i >= BATCH*Npts) return;
    int b = i / Npts, n = i - b*Npts;
    const float* w = g_w2c + b*12;
    float x = pts[(size_t)i*3], y = pts[(size_t)i*3+1], z = pts[(size_t)i*3+2];
    float camx = w[0]*x + w[1]*y + w[2]*z + w[3];
    float camy = w[4]*x + w[5]*y + w[6]*z + w[7];
    float camz = w[8]*x + w[9]*y + w[10]*z + w[11];
    float zs = (fabsf(camz) > 1e-8f) ? camz : 1e-8f;
    float fx = Kin[b*9+0], cxk = Kin[b*9+2], fy = Kin[b*9+4], cyk = Kin[b*9+5];
    float px = fx*camx/zs + cxk;
    float py = fy*camy/zs + cyk;
    int ix = (int)floorf(px), iy = (int)floorf(py);
    bool valid = (camz > 1e-6f) && ix >= 0 && ix < IMG && iy >= 0 && iy < IMG;
    int pix = valid ? iy*IMG + ix : -1;
    g_pixb[b*N1 + n] = pix;
    g_pzb[b*N1 + n] = camz;
    if (valid)
        atomicMin(&g_zbuf[((size_t)zhalf*BATCH + b)*NPIX + pix],
                  ((ull)__float_as_uint(camz) << 32) | (unsigned)n);
}

// ------------------------- gather cond + visibility check -------------------------
__global__ __launch_bounds__(128) void gather_cond(const float* __restrict__ pts,
                                                   int Npts, int zhalf){
    int blk = blockIdx.x;
    int b = blk / Npts, n = blk - b*Npts;
    int tid = threadIdx.x;
    float* xo = g_x + ((size_t)b*N1 + n)*XLD;
    if (tid < 3) xo[512 + tid] = pts[(size_t)blk*3 + tid];
    int pix = g_pixb[b*N1 + n];
    bool vis = false;
    if (pix >= 0){
        ull key = ((ull)__float_as_uint(g_pzb[b*N1 + n]) << 32) | (unsigned)n;
        vis = (g_zbuf[((size_t)zhalf*BATCH + b)*NPIX + pix] == key);
    }
    if (!vis){
        *(float4*)&xo[tid*4] = make_float4(0.f, 0.f, 0.f, 0.f);
        return;
    }
    int iy = pix / IMG, ix = pix - iy*IMG;
    float sfx = (ix + 0.5f)*(16.f/224.f) - 0.5f;
    float sfy = (iy + 0.5f)*(16.f/224.f) - 0.5f;
    int jx0 = (int)floorf(sfx); float fxw = sfx - (float)jx0;
    int jy0 = (int)floorf(sfy); float fyw = sfy - (float)jy0;
    int x0 = min(max(jx0, 0), 15), x1 = min(max(jx0+1, 0), 15);
    int y0 = min(max(jy0, 0), 15), y1 = min(max(jy0+1, 0), 15);
    float w00 = (1.f-fyw)*(1.f-fxw), w01 = (1.f-fyw)*fxw;
    float w10 = fyw*(1.f-fxw),       w11 = fyw*fxw;
    const float4* l00 = (const float4*)(g_lf + ((size_t)b*256 + y0*16 + x0)*512);
    const float4* l01 = (const float4*)(g_lf + ((size_t)b*256 + y0*16 + x1)*512);
    const float4* l10 = (const float4*)(g_lf + ((size_t)b*256 + y1*16 + x0)*512);
    const float4* l11 = (const float4*)(g_lf + ((size_t)b*256 + y1*16 + x1)*512);
    float4 v00 = l00[tid], v01 = l01[tid], v10 = l10[tid], v11 = l11[tid];
    float4 o;
    o.x = w00*v00.x + w01*v01.x + w10*v10.x + w11*v11.x;
    o.y = w00*v00.y + w01*v01.y + w10*v10.y + w11*v11.y;
    o.z = w00*v00.z + w01*v01.z + w10*v10.z + w11*v11.z;
    o.w = w00*v00.w + w01*v01.w + w10*v10.w + w11*v11.w;
    *(float4*)&xo[tid*4] = o;
}

// ------------------------- stage-0 output head + FUSED stage-1 projection (coalesced out) -------------------------
__global__ __launch_bounds__(128) void stage_out0_proj(
    const float* __restrict__ ow, const float* __restrict__ ob,
    const float* __restrict__ pts_in, float* __restrict__ pts_out,
    const float* __restrict__ Kin)
{
    __shared__ float s_ow[F0*3][DH];
    __shared__ float s_ob[F0*3];
    __shared__ __align__(16) float s_out[128*F0*3];
    const int b = blockIdx.y;
    const int tid = threadIdx.x;
    for (int i = tid; i < F0*3*DH; i += 128) s_ow[i / DH][i % DH] = ow[i];
    if (tid < F0*3) s_ob[tid] = ob[tid];
    __syncthreads();
    const int n = blockIdx.x*128 + tid;
    const float* hp = g_h + (size_t)b*DH*HLD;
    float acc[F0*3];
#pragma unroll
    for (int r = 0; r < F0*3; r++) acc[r] = s_ob[r];
    for (int o = 0; o < DH; o++){
        float hv = hp[(size_t)o*HLD + n];
#pragma unroll
        for (int r = 0; r < F0*3; r++) acc[r] += s_ow[r][o] * hv;
    }
    float p[3];
    p[0] = pts_in[(size_t)(b*N0 + n)*3 + 0];
    p[1] = pts_in[(size_t)(b*N0 + n)*3 + 1];
    p[2] = pts_in[(size_t)(b*N0 + n)*3 + 2];

    const float* w = g_w2c + b*12;
    const float fx = Kin[b*9+0], cxk = Kin[b*9+2];
    const float fy = Kin[b*9+4], cyk = Kin[b*9+5];

#pragma unroll
    for (int k = 0; k < F0; k++){
        float o3[3];
#pragma unroll
        for (int c = 0; c < 3; c++){
            o3[c] = p[c] + tanhf(acc[k*3 + c]);
            s_out[(tid*F0 + k)*3 + c] = o3[c];
        }
        float camx = w[0]*o3[0] + w[1]*o3[1] + w[2]*o3[2] + w[3];
        float camy = w[4]*o3[0] + w[5]*o3[1] + w[6]*o3[2] + w[7];
        float camz = w[8]*o3[0] + w[9]*o3[1] + w[10]*o3[2] + w[11];
        float zs = (fabsf(camz) > 1e-8f) ? camz : 1e-8f;
        float px = fx*camx/zs + cxk;
        float py = fy*camy/zs + cyk;
        int ix = (int)floorf(px), iy = (int)floorf(py);
        bool valid = (camz > 1e-6f) && ix >= 0 && ix < IMG && iy >= 0 && iy < IMG;
        int pix = valid ? iy*IMG + ix : -1;
        int idx = n*F0 + k;
        g_pixb[b*N1 + idx] = pix;
        g_pzb[b*N1 + idx] = camz;
        if (valid)
            atomicMin(&g_zbuf[((size_t)1*BATCH + b)*NPIX + pix],
                      ((ull)__float_as_uint(camz) << 32) | (unsigned)idx);
    }
    __syncthreads();
    // coalesced block write: region [(b*N0 + n0)*F0*3, +128*F0*3) is contiguous
    float* dst = pts_out + ((size_t)b*N0 + (size_t)blockIdx.x*128)*F0*3;
    const float4* src4 = (const float4*)s_out;
#pragma unroll
    for (int i = 0; i < F0*3/4*128/128; i++)   // 128*F0*3/4 = 384 float4, 3 per thread
        ;
    for (int i = tid; i < 128*F0*3/4; i += 128)
        *(float4*)(dst + i*4) = src4[i];
}

// ------------------------- stage-1 output head (coalesced out) -------------------------
template <int F>
__global__ __launch_bounds__(128) void stage_out(
    const float* __restrict__ ow, const float* __restrict__ ob,
    const float* __restrict__ pts_in, float* __restrict__ pts_out, int Npts)
{
    __shared__ float s_ow[F*3][DH];
    __shared__ float s_ob[F*3];
    __shared__ __align__(16) float s_out[128*F*3];
    const int b = blockIdx.y;
    const int tid = threadIdx.x;
    for (int i = tid; i < F*3*DH; i += 128) s_ow[i / DH][i % DH] = ow[i];
    if (tid < F*3) s_ob[tid] = ob[tid];
    __syncthreads();
    const int n = blockIdx.x*128 + tid;
    const float* hp = g_h + (size_t)b*DH*HLD;
    float acc[F*3];
#pragma unroll
    for (int r = 0; r < F*3; r++) acc[r] = s_ob[r];
    for (int o = 0; o < DH; o++){
        float hv = hp[(size_t)o*HLD + n];
#pragma unroll
        for (int r = 0; r < F*3; r++) acc[r] += s_ow[r][o] * hv;
    }
    float p[3];
    p[0] = pts_in[(size_t)(b*Npts + n)*3 + 0];
    p[1] = pts_in[(size_t)(b*Npts + n)*3 + 1];
    p[2] = pts_in[(size_t)(b*Npts + n)*3 + 2];
#pragma unroll
    for (int k = 0; k < F; k++)
#pragma unroll
        for (int c = 0; c < 3; c++)
            s_out[(tid*F + k)*3 + c] = p[c] + tanhf(acc[k*3 + c]);
    __syncthreads();
    float* dst = pts_out + ((size_t)b*Npts + (size_t)blockIdx.x*128)*F*3;
    const float4* src4 = (const float4*)s_out;
    for (int i = tid; i < 128*F*3/4; i += 128)
        *(float4*)(dst + i*4) = src4[i];
}

// ------------------------- launch -------------------------
extern "C" void kernel_launch(void* const* d_in, const int* in_sizes, int n_in,
                              void* d_out, int out_size)
{
    const float* points = (const float*)d_in[0];
    const float* tokens = (const float*)d_in[1];
    const float* c2w    = (const float*)d_in[2];
    const float* Kin    = (const float*)d_in[3];
    const float* w1     = (const float*)d_in[4];
    const float* b1     = (const float*)d_in[5];
    const float* w2     = (const float*)d_in[6];
    const float* b2     = (const float*)d_in[7];
    const float* s0w1   = (const float*)d_in[8];
    const float* s0b1   = (const float*)d_in[9];
    const float* s0ow   = (const float*)d_in[10];
    const float* s0ob   = (const float*)d_in[11];
    const float* s1w1   = (const float*)d_in[12];
    const float* s1b1   = (const float*)d_in[13];
    const float* s1ow   = (const float*)d_in[14];
    const float* s1ob   = (const float*)d_in[15];

    float* out0 = (float*)d_out;
    float* out1 = out0 + (size_t)BATCH*N0*F0*3;

    float *part, *tokT, *feat1T, *lfbuf, *w1p, *xbuf, *hbuf;
    cudaGetSymbolAddress((void**)&part,   g_part);
    cudaGetSymbolAddress((void**)&tokT,   g_tokT);
    cudaGetSymbolAddress((void**)&feat1T, g_feat1T);
    cudaGetSymbolAddress((void**)&lfbuf,  g_lf);
    cudaGetSymbolAddress((void**)&w1p,    g_w1p);
    cudaGetSymbolAddress((void**)&xbuf,   g_x);
    cudaGetSymbolAddress((void**)&hbuf,   g_h);

    // 1 — all preparation in one launch (zbuf x2, weight pad, camera, token transpose)
    prep<<<PREP_BLOCKS, 256>>>(c2w, s0w1, s1w1, tokens);

    // token MLP (token 0 dropped -> N=256)
    gemm_k<4><<<dim3(4, 16, BATCH*4), 128>>>(w1, tokT, part,
        1152/4, 1152, 1152, 256, (size_t)256*1152);
    reduce_act_T<4><<<dim3(1024/32, 256/32, BATCH), dim3(32, 8)>>>(part, b1, feat1T,
        1024, 256, 1024, (size_t)256*1024, 1);
    gemm_k<8><<<dim3(4, 8, BATCH*8), 128>>>(w2, feat1T, part,
        1024/8, 1024, 1024, 256, (size_t)256*1024);
    reduce_act_T<8><<<dim3(512/32, 256/32, BATCH), dim3(32, 8)>>>(part, b2, lfbuf,
        512, 256, 512, (size_t)256*512, 0);

    // stage 0 (zbuf half 0)
    project<<<(BATCH*N0 + 255)/256, 256>>>(points, Kin, N0, 0);
    gather_cond<<<BATCH*N0, 128>>>(points, N0, 0);
    gemm_k<4><<<dim3(8, 2, BATCH*4), 128>>>(w1p, xbuf, part,
        KPAD/4, KPAD, XLD, 512, (size_t)N1*XLD);
    reduce_act<4><<<dim3(128*512/4/256, BATCH), 256>>>(part, s0b1, hbuf,
        128, 512, HLD, (size_t)DH*HLD, 1);
    stage_out0_proj<<<dim3(N0/128, BATCH), 128>>>(s0ow, s0ob, points, out0, Kin);

    // stage 1 (projection fused into stage_out0_proj)
    gather_cond<<<BATCH*N1, 128>>>(out0, N1, 1);
    gemm_k<4><<<dim3(32, 2, BATCH*4), 128>>>(w1p + DH*KPAD, xbuf, part,
        KPAD/4, KPAD, XLD, 2048, (size_t)N1*XLD);
    reduce_act<4><<<dim3(128*2048/4/256, BATCH), 256>>>(part, s1b1, hbuf,
        128, 2048, HLD, (size_t)DH*HLD, 1);
    stage_out<F1><<<dim3(N1/128, BATCH), 128>>>(s1ow, s1ob, out0, out1, N1);
}

// round 17
// speedup vs baseline: 1.4114x; 1.0067x over previous
#include <cuda_runtime.h>
#include <math.h>
#include <stdint.h>

#define BATCH 4
#define IMG 224
#define NPIX (IMG*IMG)
#define N0 512
#define F0 4
#define N1 2048
#define F1 8
#define KPAD 576          // padded 3+512 -> 576 (Kc div by 16 at S=4 and S=9)
#define XLD 576
#define HLD 2048
#define DH 128

typedef unsigned long long ull;

// ------------------------- scratch -------------------------
__device__ float g_part[(size_t)4*4*1024*256];         // split-K partials (16.8 MB; stage0 S=9 needs 9.4 MB)
__device__ float g_tokT[(size_t)BATCH*256*1152];       // [b][n][c] transposed tokens (token0 dropped)
__device__ float g_feat1T[(size_t)BATCH*256*1024];     // [b][n][m]
__device__ float g_lf[(size_t)BATCH*256*512];          // [b][cell][c]
__device__ float g_w2c[BATCH*12];
__device__ float g_w1p[2*DH*KPAD];                     // padded/reordered stage weights
__device__ int   g_pixb[BATCH*N1];
__device__ float g_pzb[BATCH*N1];
__device__ ull   g_zbuf[(size_t)2*BATCH*NPIX];         // double-buffered (stage0 / stage1)
__device__ float g_x[(size_t)BATCH*N1*XLD];            // [b][n][k]
__device__ float g_h[(size_t)BATCH*DH*HLD];

// ------------------------- helpers -------------------------
__device__ __forceinline__ void ffma2(ull &d, ull a, ull b){
    asm("fma.rn.f32x2 %0, %1, %2, %0;" : "+l"(d) : "l"(a), "l"(b));
}
__device__ __forceinline__ float2 unpack2(ull v){
    float2 r; asm("mov.b64 {%0,%1}, %2;" : "=f"(r.x), "=f"(r.y) : "l"(v)); return r;
}

// ------------------------- k-pair packed-fp32 split-K GEMM, 64x64 tile, KTILE=16 -------------------------
// (R7 core verbatim — known-good at 4 blocks/SM, regs 128, no spills.)
template<int S>
__global__ __launch_bounds__(128, 4) void gemm_k(
    const float* __restrict__ A, const float* __restrict__ B,
    float* __restrict__ Cpart, int Kc, int lda, int ldb, int N, size_t sB)
{
    __shared__ __align__(16) float As[2][8][128];
    __shared__ __align__(16) float Bs[2][8][256];
    const int tid = threadIdx.x;
    const int m0 = blockIdx.y * 64;
    const int n0 = blockIdx.x * 64;
    const int M  = gridDim.y * 64;
    const int bz = blockIdx.z;
    const int b  = bz / S, s = bz % S;
    float* Cp = Cpart + (size_t)bz * ((size_t)M * N);
    const int tm = tid >> 4, tn = tid & 15;
    const int lm = tid & 63, lh = tid >> 6;

    const float* Ap = A + (size_t)(m0 + lm) * lda + (size_t)s * Kc + lh*8;
    const float* Bp = B + (size_t)b * sB + (size_t)(n0 + lm) * ldb + (size_t)s * Kc + lh*8;

    ull acc[8][4];
#pragma unroll
    for (int i = 0; i < 8; i++)
#pragma unroll
        for (int j = 0; j < 4; j++) acc[i][j] = 0ULL;

    float4 pa, pb;
    auto ldSet = [&](int tI, int set){
        pa = *(const float4*)(Ap + tI*16 + set*4);
        pb = *(const float4*)(Bp + tI*16 + set*4);
    };
    auto stSet = [&](int buf, int set){
        int kp = lh*4 + set*2;
        *(float2*)&As[buf][kp  ][2*lm] = make_float2(pa.x, pa.y);
        *(float2*)&As[buf][kp+1][2*lm] = make_float2(pa.z, pa.w);
        *(float2*)&Bs[buf][kp  ][2*lm] = make_float2(pb.x, pb.y);
        *(float2*)&Bs[buf][kp+1][2*lm] = make_float2(pb.z, pb.w);
    };
    auto compute = [&](int cur, int h){
        const float* asP = &As[cur][0][16*tm];
        const float* bsP = &Bs[cur][0][4*tn];
#pragma unroll
        for (int kp = 4*h; kp < 4*h + 4; ++kp){
            ull av[8];
#pragma unroll
            for (int i = 0; i < 4; i++){
                longlong2 aa = *(const longlong2*)(asP + kp*128 + 4*i);
                av[2*i] = (ull)aa.x; av[2*i+1] = (ull)aa.y;
            }
            ull bv[4];
#pragma unroll
            for (int q = 0; q < 2; q++){
                longlong2 bb = *(const longlong2*)(bsP + kp*256 + 64*q);
                bv[2*q] = (ull)bb.x; bv[2*q+1] = (ull)bb.y;
            }
#pragma unroll
            for (int i = 0; i < 8; i++)
#pragma unroll
                for (int j = 0; j < 4; j++) ffma2(acc[i][j], av[i], bv[j]);
        }
    };

    ldSet(0, 0); stSet(0, 0);
    ldSet(0, 1); stSet(0, 1);
    __syncthreads();

    const int T = Kc / 16;
    for (int t = 0; t < T; ++t){
        const int cur = t & 1, nxt = cur ^ 1;
        const int tN = (t + 1 < T) ? (t + 1) : t;
        ldSet(tN, 0);
        compute(cur, 0);
        stSet(nxt, 0);
        ldSet(tN, 1);
        compute(cur, 1);
        stSet(nxt, 1);
        __syncthreads();
    }

#pragma unroll
    for (int i = 0; i < 8; i++){
        int m = m0 + tm*8 + i;
#pragma unroll
        for (int q = 0; q < 2; q++){
            float2 v0 = unpack2(acc[i][2*q]);
            float2 v1 = unpack2(acc[i][2*q+1]);
            int n = n0 + 2*tn + 32*q;
            *(float2*)&Cp[(size_t)m*N + n] = make_float2(v0.x + v0.y, v1.x + v1.y);
        }
    }
}

// ------------------------- split-K reduce + bias + activation (row-major out) -------------------------
template<int S>
__global__ __launch_bounds__(256) void reduce_act(
    const float* __restrict__ part, const float* __restrict__ bias,
    float* __restrict__ C, int M, int N, int ldc, size_t sC, int relu)
{
    const int b = blockIdx.y;
    const int idx = blockIdx.x*256 + threadIdx.x;
    const int total = M*N/4;
    if (idx >= total) return;
    const int m = (idx*4) / N, n = (idx*4) % N;
    const float4* p = (const float4*)(part + (size_t)b*S*M*N);
    float4 a = p[idx];
#pragma unroll
    for (int s = 1; s < S; s++){
        float4 v = p[idx + (size_t)s*total];
        a.x += v.x; a.y += v.y; a.z += v.z; a.w += v.w;
    }
    float bv = bias[m];
    a.x += bv; a.y += bv; a.z += bv; a.w += bv;
    if (relu){
        a.x = fmaxf(a.x, 0.f); a.y = fmaxf(a.y, 0.f);
        a.z = fmaxf(a.z, 0.f); a.w = fmaxf(a.w, 0.f);
    }
    *(float4*)&C[(size_t)b*sC + (size_t)m*ldc + n] = a;
}

// ------------------------- split-K reduce + bias + act + TRANSPOSE (out[n][m]) -------------------------
template<int S>
__global__ void reduce_act_T(
    const float* __restrict__ part, const float* __restrict__ bias,
    float* __restrict__ outT, int M, int N, int ldo, size_t sO, int relu)
{
    __shared__ float sm[32][33];
    const int b = blockIdx.z;
    const int m0 = blockIdx.x*32, n0 = blockIdx.y*32;
    const int x = threadIdx.x, y = threadIdx.y;
    const float* p = part + (size_t)b*S*M*N;
#pragma unroll
    for (int r = 0; r < 32; r += 8){
        int m = m0 + y + r;
        float a = 0.f;
        for (int s = 0; s < S; s++) a += p[(size_t)s*M*N + (size_t)m*N + n0 + x];
        a += bias[m];
        if (relu) a = fmaxf(a, 0.f);
        sm[y+r][x] = a;
    }
    __syncthreads();
#pragma unroll
    for (int r = 0; r < 32; r += 8)
        outT[(size_t)b*sO + (size_t)(n0 + y + r)*ldo + m0 + x] = sm[x][y+r];
}

// ------------------------- fused prep: zbuf resets + pad_w + setup_w2c + transpose_tok -------------------------
#define ZBLKS  (2*BATCH*NPIX/256)        // 1568 (exact)
#define PWBLKS (2*DH*KPAD/256)           // 576 (exact)
#define TTBLKS (8*36*BATCH)              // 1152
#define PREP_BLOCKS (ZBLKS + PWBLKS + 1 + TTBLKS)

__global__ void prep(const float* __restrict__ c2w,
                     const float* __restrict__ w0, const float* __restrict__ w1s,
                     const float* __restrict__ tokens)
{
    __shared__ float sm[32][33];
    int blk = blockIdx.x;
    const int tid = threadIdx.x;

    if (blk < ZBLKS){                      // zero both z-buffers
        g_zbuf[(size_t)blk*256 + tid] = ~0ULL;
        return;
    }
    blk -= ZBLKS;
    if (blk < PWBLKS){                     // pad/reorder stage weights
        int i = blk*256 + tid;
        int s = i / (DH*KPAD);
        int r = i - s*(DH*KPAD);
        int m = r / KPAD, k = r - m*KPAD;
        const float* w = s ? w1s : w0;
        float v = 0.f;
        if (k < 512) v = w[m*515 + 3 + k];
        else if (k < 515) v = w[m*515 + (k - 512)];
        g_w1p[i] = v;
        return;
    }
    blk -= PWBLKS;
    if (blk == 0){                         // camera inverse
        int b = tid;
        if (b >= BATCH) return;
        float m[4][4], inv[4][4];
        for (int r = 0; r < 4; r++)
            for (int c = 0; c < 4; c++){
                float v = c2w[b*16 + r*4 + c];
                if (r < 3 && (c == 1 || c == 2)) v = -v;
                m[r][c] = v;
                inv[r][c] = (r == c) ? 1.f : 0.f;
            }
        for (int col = 0; col < 4; col++){
            int piv = col; float best = fabsf(m[col][col]);
            for (int r = col+1; r < 4; r++){ float a = fabsf(m[r][col]); if (a > best){ best = a; piv = r; } }
            if (piv != col)
                for (int c = 0; c < 4; c++){
                    float t = m[col][c]; m[col][c] = m[piv][c]; m[piv][c] = t;
                    t = inv[col][c]; inv[col][c] = inv[piv][c]; inv[piv][c] = t;
                }
            float d = 1.f / m[col][col];
            for (int c = 0; c < 4; c++){ m[col][c] *= d; inv[col][c] *= d; }
            for (int r = 0; r < 4; r++)
                if (r != col){
                    float f = m[r][col];
                    for (int c = 0; c < 4; c++){ m[r][c] -= f*m[col][c]; inv[r][c] -= f*inv[col][c]; }
                }
        }
        for (int i = 0; i < 12; i++) g_w2c[b*12 + i] = inv[i/4][i%4];
        return;
    }
    blk -= 1;
    {                                      // transpose tokens (token0 dropped)
        int n0 = (blk & 7)*32;
        int c0 = ((blk >> 3) % 36)*32;
        int b  = blk / 288;
        int x = tid & 31, y = tid >> 5;
#pragma unroll
        for (int r = 0; r < 32; r += 8)
            sm[y+r][x] = tokens[((size_t)b*1152 + c0 + y + r)*257 + n0 + x + 1];
        __syncthreads();
#pragma unroll
        for (int r = 0; r < 32; r += 8)
            g_tokT[((size_t)b*256 + n0 + y + r)*1152 + c0 + x] = sm[x][y+r];
    }
}

// ------------------------- z-buffer projection -------------------------
__global__ void project(const float* __restrict__ pts, const float* __restrict__ Kin,
                        int Npts, int zhalf){
    int i = blockIdx.x*256 + threadIdx.x;
    if (i >= BATCH*Npts) return;
    int b = i / Npts, n = i - b*Npts;
    const float* w = g_w2c + b*12;
    float x = pts[(size_t)i*3], y = pts[(size_t)i*3+1], z = pts[(size_t)i*3+2];
    float camx = w[0]*x + w[1]*y + w[2]*z + w[3];
    float camy = w[4]*x + w[5]*y + w[6]*z + w[7];
    float camz = w[8]*x + w[9]*y + w[10]*z + w[11];
    float zs = (fabsf(camz) > 1e-8f) ? camz : 1e-8f;
    float fx = Kin[b*9+0], cxk = Kin[b*9+2], fy = Kin[b*9+4], cyk = Kin[b*9+5];
    float px = fx*camx/zs + cxk;
    float py = fy*camy/zs + cyk;
    int ix = (int)floorf(px), iy = (int)floorf(py);
    bool valid = (camz > 1e-6f) && ix >= 0 && ix < IMG && iy >= 0 && iy < IMG;
    int pix = valid ? iy*IMG + ix : -1;
    g_pixb[b*N1 + n] = pix;
    g_pzb[b*N1 + n] = camz;
    if (valid)
        atomicMin(&g_zbuf[((size_t)zhalf*BATCH + b)*NPIX + pix],
                  ((ull)__float_as_uint(camz) << 32) | (unsigned)n);
}

// ------------------------- gather cond + visibility check -------------------------
__global__ __launch_bounds__(128) void gather_cond(const float* __restrict__ pts,
                                                   int Npts, int zhalf){
    int blk = blockIdx.x;
    int b = blk / Npts, n = blk - b*Npts;
    int tid = threadIdx.x;
    float* xo = g_x + ((size_t)b*N1 + n)*XLD;
    if (tid < 3) xo[512 + tid] = pts[(size_t)blk*3 + tid];
    int pix = g_pixb[b*N1 + n];
    bool vis = false;
    if (pix >= 0){
        ull key = ((ull)__float_as_uint(g_pzb[b*N1 + n]) << 32) | (unsigned)n;
        vis = (g_zbuf[((size_t)zhalf*BATCH + b)*NPIX + pix] == key);
    }
    if (!vis){
        *(float4*)&xo[tid*4] = make_float4(0.f, 0.f, 0.f, 0.f);
        return;
    }
    int iy = pix / IMG, ix = pix - iy*IMG;
    float sfx = (ix + 0.5f)*(16.f/224.f) - 0.5f;
    float sfy = (iy + 0.5f)*(16.f/224.f) - 0.5f;
    int jx0 = (int)floorf(sfx); float fxw = sfx - (float)jx0;
    int jy0 = (int)floorf(sfy); float fyw = sfy - (float)jy0;
    int x0 = min(max(jx0, 0), 15), x1 = min(max(jx0+1, 0), 15);
    int y0 = min(max(jy0, 0), 15), y1 = min(max(jy0+1, 0), 15);
    float w00 = (1.f-fyw)*(1.f-fxw), w01 = (1.f-fyw)*fxw;
    float w10 = fyw*(1.f-fxw),       w11 = fyw*fxw;
    const float4* l00 = (const float4*)(g_lf + ((size_t)b*256 + y0*16 + x0)*512);
    const float4* l01 = (const float4*)(g_lf + ((size_t)b*256 + y0*16 + x1)*512);
    const float4* l10 = (const float4*)(g_lf + ((size_t)b*256 + y1*16 + x0)*512);
    const float4* l11 = (const float4*)(g_lf + ((size_t)b*256 + y1*16 + x1)*512);
    float4 v00 = l00[tid], v01 = l01[tid], v10 = l10[tid], v11 = l11[tid];
    float4 o;
    o.x = w00*v00.x + w01*v01.x + w10*v10.x + w11*v11.x;
    o.y = w00*v00.y + w01*v01.y + w10*v10.y + w11*v11.y;
    o.z = w00*v00.z + w01*v01.z + w10*v10.z + w11*v11.z;
    o.w = w00*v00.w + w01*v01.w + w10*v10.w + w11*v11.w;
    *(float4*)&xo[tid*4] = o;
}

// ------------------------- stage-0 output head + FUSED stage-1 projection (coalesced out) -------------------------
__global__ __launch_bounds__(128) void stage_out0_proj(
    const float* __restrict__ ow, const float* __restrict__ ob,
    const float* __restrict__ pts_in, float* __restrict__ pts_out,
    const float* __restrict__ Kin)
{
    __shared__ float s_ow[F0*3][DH];
    __shared__ float s_ob[F0*3];
    __shared__ __align__(16) float s_out[128*F0*3];
    const int b = blockIdx.y;
    const int tid = threadIdx.x;
    for (int i = tid; i < F0*3*DH; i += 128) s_ow[i / DH][i % DH] = ow[i];
    if (tid < F0*3) s_ob[tid] = ob[tid];
    __syncthreads();
    const int n = blockIdx.x*128 + tid;
    const float* hp = g_h + (size_t)b*DH*HLD;
    float acc[F0*3];
#pragma unroll
    for (int r = 0; r < F0*3; r++) acc[r] = s_ob[r];
    for (int o = 0; o < DH; o++){
        float hv = hp[(size_t)o*HLD + n];
#pragma unroll
        for (int r = 0; r < F0*3; r++) acc[r] += s_ow[r][o] * hv;
    }
    float p[3];
    p[0] = pts_in[(size_t)(b*N0 + n)*3 + 0];
    p[1] = pts_in[(size_t)(b*N0 + n)*3 + 1];
    p[2] = pts_in[(size_t)(b*N0 + n)*3 + 2];

    const float* w = g_w2c + b*12;
    const float fx = Kin[b*9+0], cxk = Kin[b*9+2];
    const float fy = Kin[b*9+4], cyk = Kin[b*9+5];

#pragma unroll
    for (int k = 0; k < F0; k++){
        float o3[3];
#pragma unroll
        for (int c = 0; c < 3; c++){
            o3[c] = p[c] + tanhf(acc[k*3 + c]);
            s_out[(tid*F0 + k)*3 + c] = o3[c];
        }
        float camx = w[0]*o3[0] + w[1]*o3[1] + w[2]*o3[2] + w[3];
        float camy = w[4]*o3[0] + w[5]*o3[1] + w[6]*o3[2] + w[7];
        float camz = w[8]*o3[0] + w[9]*o3[1] + w[10]*o3[2] + w[11];
        float zs = (fabsf(camz) > 1e-8f) ? camz : 1e-8f;
        float px = fx*camx/zs + cxk;
        float py = fy*camy/zs + cyk;
        int ix = (int)floorf(px), iy = (int)floorf(py);
        bool valid = (camz > 1e-6f) && ix >= 0 && ix < IMG && iy >= 0 && iy < IMG;
        int pix = valid ? iy*IMG + ix : -1;
        int idx = n*F0 + k;
        g_pixb[b*N1 + idx] = pix;
        g_pzb[b*N1 + idx] = camz;
        if (valid)
            atomicMin(&g_zbuf[((size_t)1*BATCH + b)*NPIX + pix],
                      ((ull)__float_as_uint(camz) << 32) | (unsigned)idx);
    }
    __syncthreads();
    float* dst = pts_out + ((size_t)b*N0 + (size_t)blockIdx.x*128)*F0*3;
    const float4* src4 = (const float4*)s_out;
    for (int i = tid; i < 128*F0*3/4; i += 128)
        *(float4*)(dst + i*4) = src4[i];
}

// ------------------------- stage-1 output head (coalesced out) -------------------------
template <int F>
__global__ __launch_bounds__(128) void stage_out(
    const float* __restrict__ ow, const float* __restrict__ ob,
    const float* __restrict__ pts_in, float* __restrict__ pts_out, int Npts)
{
    __shared__ float s_ow[F*3][DH];
    __shared__ float s_ob[F*3];
    __shared__ __align__(16) float s_out[128*F*3];
    const int b = blockIdx.y;
    const int tid = threadIdx.x;
    for (int i = tid; i < F*3*DH; i += 128) s_ow[i / DH][i % DH] = ow[i];
    if (tid < F*3) s_ob[tid] = ob[tid];
    __syncthreads();
    const int n = blockIdx.x*128 + tid;
    const float* hp = g_h + (size_t)b*DH*HLD;
    float acc[F*3];
#pragma unroll
    for (int r = 0; r < F*3; r++) acc[r] = s_ob[r];
    for (int o = 0; o < DH; o++){
        float hv = hp[(size_t)o*HLD + n];
#pragma unroll
        for (int r = 0; r < F*3; r++) acc[r] += s_ow[r][o] * hv;
    }
    float p[3];
    p[0] = pts_in[(size_t)(b*Npts + n)*3 + 0];
    p[1] = pts_in[(size_t)(b*Npts + n)*3 + 1];
    p[2] = pts_in[(size_t)(b*Npts + n)*3 + 2];
#pragma unroll
    for (int k = 0; k < F; k++)
#pragma unroll
        for (int c = 0; c < 3; c++)
            s_out[(tid*F + k)*3 + c] = p[c] + tanhf(acc[k*3 + c]);
    __syncthreads();
    float* dst = pts_out + ((size_t)b*Npts + (size_t)blockIdx.x*128)*F*3;
    const float4* src4 = (const float4*)s_out;
    for (int i = tid; i < 128*F*3/4; i += 128)
        *(float4*)(dst + i*4) = src4[i];
}

// ------------------------- launch -------------------------
extern "C" void kernel_launch(void* const* d_in, const int* in_sizes, int n_in,
                              void* d_out, int out_size)
{
    const float* points = (const float*)d_in[0];
    const float* tokens = (const float*)d_in[1];
    const float* c2w    = (const float*)d_in[2];
    const float* Kin    = (const float*)d_in[3];
    const float* w1     = (const float*)d_in[4];
    const float* b1     = (const float*)d_in[5];
    const float* w2     = (const float*)d_in[6];
    const float* b2     = (const float*)d_in[7];
    const float* s0w1   = (const float*)d_in[8];
    const float* s0b1   = (const float*)d_in[9];
    const float* s0ow   = (const float*)d_in[10];
    const float* s0ob   = (const float*)d_in[11];
    const float* s1w1   = (const float*)d_in[12];
    const float* s1b1   = (const float*)d_in[13];
    const float* s1ow   = (const float*)d_in[14];
    const float* s1ob   = (const float*)d_in[15];

    float* out0 = (float*)d_out;
    float* out1 = out0 + (size_t)BATCH*N0*F0*3;

    float *part, *tokT, *feat1T, *lfbuf, *w1p, *xbuf, *hbuf;
    cudaGetSymbolAddress((void**)&part,   g_part);
    cudaGetSymbolAddress((void**)&tokT,   g_tokT);
    cudaGetSymbolAddress((void**)&feat1T, g_feat1T);
    cudaGetSymbolAddress((void**)&lfbuf,  g_lf);
    cudaGetSymbolAddress((void**)&w1p,    g_w1p);
    cudaGetSymbolAddress((void**)&xbuf,   g_x);
    cudaGetSymbolAddress((void**)&hbuf,   g_h);

    // 1 — all preparation in one launch (zbuf x2, weight pad, camera, token transpose)
    prep<<<PREP_BLOCKS, 256>>>(c2w, s0w1, s1w1, tokens);

    // token MLP (token 0 dropped -> N=256)
    gemm_k<4><<<dim3(4, 16, BATCH*4), 128>>>(w1, tokT, part,
        1152/4, 1152, 1152, 256, (size_t)256*1152);
    reduce_act_T<4><<<dim3(1024/32, 256/32, BATCH), dim3(32, 8)>>>(part, b1, feat1T,
        1024, 256, 1024, (size_t)256*1024, 1);
    gemm_k<8><<<dim3(4, 8, BATCH*8), 128>>>(w2, feat1T, part,
        1024/8, 1024, 1024, 256, (size_t)256*1024);
    reduce_act_T<8><<<dim3(512/32, 256/32, BATCH), dim3(32, 8)>>>(part, b2, lfbuf,
        512, 256, 512, (size_t)256*512, 0);

    // stage 0 (zbuf half 0) — split-K 9 fills ~one full wave (576 blocks)
    project<<<(BATCH*N0 + 255)/256, 256>>>(points, Kin, N0, 0);
    gather_cond<<<BATCH*N0, 128>>>(points, N0, 0);
    gemm_k<9><<<dim3(8, 2, BATCH*9), 128>>>(w1p, xbuf, part,
        KPAD/9, KPAD, XLD, 512, (size_t)N1*XLD);
    reduce_act<9><<<dim3(128*512/4/256, BATCH), 256>>>(part, s0b1, hbuf,
        128, 512, HLD, (size_t)DH*HLD, 1);
    stage_out0_proj<<<dim3(N0/128, BATCH), 128>>>(s0ow, s0ob, points, out0, Kin);

    // stage 1 (projection fused into stage_out0_proj)
    gather_cond<<<BATCH*N1, 128>>>(out0, N1, 1);
    gemm_k<4><<<dim3(32, 2, BATCH*4), 128>>>(w1p + DH*KPAD, xbuf, part,
        KPAD/4, KPAD, XLD, 2048, (size_t)N1*XLD);
    reduce_act<4><<<dim3(128*2048/4/256, BATCH), 256>>>(part, s1b1, hbuf,
        128, 2048, HLD, (size_t)DH*HLD, 1);
    stage_out<F1><<<dim3(N1/128, BATCH), 128>>>(s1ow, s1ob, out0, out1, N1);
}